// round 8
// baseline (speedup 1.0000x reference)
#include <cuda_runtime.h>
#include <cuda_fp16.h>
#include <cstdint>

#define NN  100000
#define DD  128
#define EE  3200000
#define SCAN_B 98            // ceil(100000/1024)
#define GEMM_TILES 782       // ceil(100000/128)
#define XS_STRIDE 132        // padded row stride (floats) -> conflict-free frags
#define GEMM_SMEM (2 * 128 * XS_STRIDE * 4)   // Ws + Xs = 135168 B

// Scratch (static device arrays; no allocs allowed)
__device__ float  g_dinv[NN];
__device__ __half g_h16[(size_t)NN * DD];     // 25.6 MB (gather payload)
__device__ int    g_count[NN];
__device__ int    g_off[NN + 1];
__device__ int    g_cur[NN];
__device__ int    g_bsum[SCAN_B];
__device__ int    g_bpref[SCAN_B];
__device__ int2   g_csr[EE];                  // (src, w bits) 25.6 MB

__device__ __forceinline__ unsigned f2tf32(float f) {
    unsigned u;
    asm("cvt.rna.tf32.f32 %0, %1;" : "=r"(u) : "f"(f));
    return u;
}

// ---------------------------------------------------------------------------
__global__ void k_init() {
    int i = blockIdx.x * blockDim.x + threadIdx.x;
    if (i < NN) g_count[i] = 0;
}

// ---------------------------------------------------------------------------
// count[dst]++   (4 edges per thread; no weight read, no float atomic)
// ---------------------------------------------------------------------------
__global__ void k_count(const int* __restrict__ dst, int E4) {
    int i = blockIdx.x * blockDim.x + threadIdx.x;
    if (i >= E4) return;
    const int4 d4 = ((const int4*)dst)[i];
    #pragma unroll
    for (int j = 0; j < 4; j++) {
        unsigned d = (unsigned)(&d4.x)[j];
        if (d < NN) atomicAdd(&g_count[d], 1);
    }
}

// ---------------------------------------------------------------------------
// Scan stage 1: per-block sums (98 blocks x 1024)
// ---------------------------------------------------------------------------
__global__ void k_scan1() {
    __shared__ int swarp[32];
    const int t = threadIdx.x;
    const int idx = blockIdx.x * 1024 + t;
    int v = (idx < NN) ? g_count[idx] : 0;
    #pragma unroll
    for (int o = 16; o > 0; o >>= 1) v += __shfl_down_sync(~0u, v, o);
    if ((t & 31) == 0) swarp[t >> 5] = v;
    __syncthreads();
    if (t < 32) {
        int ss = swarp[t];
        #pragma unroll
        for (int o = 16; o > 0; o >>= 1) ss += __shfl_down_sync(~0u, ss, o);
        if (t == 0) g_bsum[blockIdx.x] = ss;
    }
}

__global__ void k_scan2() {
    __shared__ int s[128];
    const int t = threadIdx.x;
    s[t] = (t < SCAN_B) ? g_bsum[t] : 0;
    __syncthreads();
    #pragma unroll
    for (int o = 1; o < 128; o <<= 1) {
        int v = (t >= o) ? s[t - o] : 0;
        __syncthreads();
        s[t] += v;
        __syncthreads();
    }
    if (t < SCAN_B) g_bpref[t] = (t == 0) ? 0 : s[t - 1];
    if (t == 127) g_off[NN] = s[127];
}

__global__ void k_scan3() {
    __shared__ int swarp[33];
    const int t = threadIdx.x;
    const int lane = t & 31;
    const int wid = t >> 5;
    const int idx = blockIdx.x * 1024 + t;
    const int val = (idx < NN) ? g_count[idx] : 0;

    int v = val;
    #pragma unroll
    for (int o = 1; o < 32; o <<= 1) {
        int n = __shfl_up_sync(~0u, v, o);
        if (lane >= o) v += n;
    }
    if (lane == 31) swarp[wid] = v;
    __syncthreads();
    if (t < 32) {
        int s = swarp[t];
        #pragma unroll
        for (int o = 1; o < 32; o <<= 1) {
            int n = __shfl_up_sync(~0u, s, o);
            if (t >= o) s += n;
        }
        swarp[t + 1] = s;
        if (t == 0) swarp[0] = 0;
    }
    __syncthreads();

    if (idx < NN) {
        int excl = g_bpref[blockIdx.x] + swarp[wid] + (v - val);
        g_off[idx] = excl;
        g_cur[idx] = excl;
    }
}

// ---------------------------------------------------------------------------
// CSR fill — g_csr[pos] = (src, raw w bits). No dinv dependency.
// ---------------------------------------------------------------------------
__global__ void k_fill(const int* __restrict__ src,
                       const int* __restrict__ dst,
                       const float* __restrict__ w, int E4) {
    int i = blockIdx.x * blockDim.x + threadIdx.x;
    if (i >= E4) return;
    const int4   s4 = ((const int4*)src)[i];
    const int4   d4 = ((const int4*)dst)[i];
    const float4 w4 = ((const float4*)w)[i];
    #pragma unroll
    for (int j = 0; j < 4; j++) {
        unsigned s = (unsigned)(&s4.x)[j];
        unsigned d = (unsigned)(&d4.x)[j];
        if (s >= NN || d >= NN) continue;
        int pos = atomicAdd(&g_cur[d], 1);
        g_csr[pos] = make_int2((int)s, __float_as_int((&w4.x)[j]));
    }
}

// ---------------------------------------------------------------------------
// degsum: warp per node — deg = 1 + sum(w over csr range); dinv = rsqrt(deg)
// ---------------------------------------------------------------------------
__global__ void k_degsum() {
    const int node = (blockIdx.x * blockDim.x + threadIdx.x) >> 5;
    const int lane = threadIdx.x & 31;
    if (node >= NN) return;
    const int beg = g_off[node];
    const int end = g_off[node + 1];
    float s = 0.0f;
    for (int e = beg + lane; e < end; e += 32)
        s += __int_as_float(g_csr[e].y);
    #pragma unroll
    for (int o = 16; o > 0; o >>= 1) s += __shfl_down_sync(~0u, s, o);
    if (lane == 0) g_dinv[node] = rsqrtf(1.0f + s);
}

// ---------------------------------------------------------------------------
// GEMM (tf32 tensor cores): h16 = fp16(x @ W).
// Block: 256 thr (8 warps, 4m x 2n). Block tile 128x128. mma.m16n8k8.
// ---------------------------------------------------------------------------
__global__ void __launch_bounds__(256, 1)
k_gemm(const float* __restrict__ x, const float* __restrict__ W) {
    extern __shared__ char smem[];
    unsigned* Ws = (unsigned*)smem;                          // [128][132] tf32
    float*    Xs = (float*)(smem + 128 * XS_STRIDE * 4);     // [128][132] fp32

    const int t    = threadIdx.x;
    const int lane = t & 31;
    const int wid  = t >> 5;
    const int wm   = wid & 3;          // 0..3  -> m offset wm*32
    const int wn   = wid >> 2;         // 0..1  -> n offset wn*64
    const int grp  = lane >> 2;        // 0..7
    const int qd   = lane & 3;         // 0..3

    // Stage W as tf32 (once per block): Ws[k][n]
    for (int i = 0; i < 64; i++) {
        int lin = i * 256 + t;
        int k = lin >> 7, n = lin & 127;
        Ws[k * XS_STRIDE + n] = f2tf32(W[lin]);
    }

    for (int tile = blockIdx.x; tile < GEMM_TILES; tile += gridDim.x) {
        const int row0 = tile * 128;

        __syncthreads();   // protect Xs/Ws from prior readers
        // Stage X tile: 128 rows x 128 cols (guarded, zero-fill)
        #pragma unroll
        for (int i = 0; i < 16; i++) {
            int lin  = i * 256 + t;
            int row  = lin >> 5;
            int col4 = lin & 31;
            float4 v = make_float4(0.f, 0.f, 0.f, 0.f);
            if (row0 + row < NN)
                v = ((const float4*)(x + (size_t)(row0 + row) * DD))[col4];
            *(float4*)(Xs + row * XS_STRIDE + col4 * 4) = v;
        }
        __syncthreads();

        float c[2][8][4];
        #pragma unroll
        for (int mt = 0; mt < 2; mt++)
            #pragma unroll
            for (int nt = 0; nt < 8; nt++)
                #pragma unroll
                for (int q = 0; q < 4; q++) c[mt][nt][q] = 0.0f;

        #pragma unroll
        for (int ks = 0; ks < 16; ks++) {
            unsigned a[2][4];
            #pragma unroll
            for (int mt = 0; mt < 2; mt++) {
                const int rb = wm * 32 + mt * 16 + grp;
                const int kb = ks * 8 + qd;
                a[mt][0] = f2tf32(Xs[rb * XS_STRIDE + kb]);
                a[mt][1] = f2tf32(Xs[(rb + 8) * XS_STRIDE + kb]);
                a[mt][2] = f2tf32(Xs[rb * XS_STRIDE + kb + 4]);
                a[mt][3] = f2tf32(Xs[(rb + 8) * XS_STRIDE + kb + 4]);
            }
            #pragma unroll
            for (int nt = 0; nt < 8; nt++) {
                const int nb = wn * 64 + nt * 8 + grp;
                const unsigned b0 = Ws[(ks * 8 + qd) * XS_STRIDE + nb];
                const unsigned b1 = Ws[(ks * 8 + qd + 4) * XS_STRIDE + nb];
                #pragma unroll
                for (int mt = 0; mt < 2; mt++) {
                    asm volatile(
                        "mma.sync.aligned.m16n8k8.row.col.f32.tf32.tf32.f32 "
                        "{%0,%1,%2,%3}, {%4,%5,%6,%7}, {%8,%9}, {%0,%1,%2,%3};"
                        : "+f"(c[mt][nt][0]), "+f"(c[mt][nt][1]),
                          "+f"(c[mt][nt][2]), "+f"(c[mt][nt][3])
                        : "r"(a[mt][0]), "r"(a[mt][1]), "r"(a[mt][2]), "r"(a[mt][3]),
                          "r"(b0), "r"(b1));
                }
            }
        }

        // Epilogue: fp16 h16 stores (half2 per C pair, cols 2*qd|+1 contiguous)
        #pragma unroll
        for (int mt = 0; mt < 2; mt++) {
            const int r0g = row0 + wm * 32 + mt * 16 + grp;
            #pragma unroll
            for (int nt = 0; nt < 8; nt++) {
                const int col = wn * 64 + nt * 8 + 2 * qd;
                if (r0g < NN) {
                    __half2 h = __float22half2_rn(make_float2(c[mt][nt][0], c[mt][nt][1]));
                    *(__half2*)(g_h16 + (size_t)r0g * DD + col) = h;
                }
                if (r0g + 8 < NN) {
                    __half2 h = __float22half2_rn(make_float2(c[mt][nt][2], c[mt][nt][3]));
                    *(__half2*)(g_h16 + (size_t)(r0g + 8) * DD + col) = h;
                }
            }
        }
    }
}

// ---------------------------------------------------------------------------
// agg — one warp per node:
// out = b + dinv*(dinv*h16[node] + sum_e w_e*dinv[src_e]*h16[src_e]).
// ---------------------------------------------------------------------------
__global__ void k_agg(float* __restrict__ out, const float* __restrict__ b) {
    const int node = (blockIdx.x * blockDim.x + threadIdx.x) >> 5;
    const int lane = threadIdx.x & 31;
    if (node >= NN) return;

    const int beg = g_off[node];
    const int end = g_off[node + 1];
    const float dd = g_dinv[node];

    float4 acc;
    {
        const uint2 hv = ((const uint2*)(g_h16 + (size_t)node * DD))[lane];
        const float2 v0 = __half22float2(*(const __half2*)&hv.x);
        const float2 v1 = __half22float2(*(const __half2*)&hv.y);
        acc.x = dd * v0.x; acc.y = dd * v0.y;
        acc.z = dd * v1.x; acc.w = dd * v1.y;
    }

    #pragma unroll 4
    for (int e = beg; e < end; e++) {
        const int2  p  = g_csr[e];
        const float nm = __int_as_float(p.y) * g_dinv[p.x];
        const uint2 hv = ((const uint2*)(g_h16 + (size_t)p.x * DD))[lane];
        const float2 v0 = __half22float2(*(const __half2*)&hv.x);
        const float2 v1 = __half22float2(*(const __half2*)&hv.y);
        acc.x += nm * v0.x;
        acc.y += nm * v0.y;
        acc.z += nm * v1.x;
        acc.w += nm * v1.y;
    }

    const float4 b4 = ((const float4*)b)[lane];
    float4 o;
    o.x = b4.x + dd * acc.x;
    o.y = b4.y + dd * acc.y;
    o.z = b4.z + dd * acc.z;
    o.w = b4.w + dd * acc.w;
    ((float4*)(out + (size_t)node * DD))[lane] = o;
}

// ---------------------------------------------------------------------------
extern "C" void kernel_launch(void* const* d_in, const int* in_sizes, int n_in,
                              void* d_out, int out_size) {
    const float* x  = nullptr;
    const int*   ei = nullptr;
    const float* ew = nullptr;
    const float* W  = nullptr;
    const float* b  = nullptr;
    int E = 0;
    for (int i = 0; i < n_in; i++) {
        const int sz = in_sizes[i];
        if      (sz == NN * DD)   x  = (const float*)d_in[i];
        else if (sz == 2 * EE)    ei = (const int*)d_in[i];
        else if (sz == EE)        { ew = (const float*)d_in[i]; E = sz; }
        else if (sz == DD * DD)   W  = (const float*)d_in[i];
        else if (sz == DD)        b  = (const float*)d_in[i];
    }
    if (!x || !ei || !ew || !W || !b) return;

    float* out = (float*)d_out;
    const int* src = ei;
    const int* dst = ei + E;
    const int E4 = E / 4;

    static cudaStream_t s2 = nullptr;
    static cudaEvent_t evFork = nullptr, evGemm = nullptr;
    static bool setup = false;
    if (!setup) {
        cudaFuncSetAttribute(k_gemm, cudaFuncAttributeMaxDynamicSharedMemorySize,
                             GEMM_SMEM);
        cudaStreamCreateWithFlags(&s2, cudaStreamNonBlocking);
        cudaEventCreateWithFlags(&evFork, cudaEventDisableTiming);
        cudaEventCreateWithFlags(&evGemm, cudaEventDisableTiming);
        setup = true;
    }

    // Fork: tensor-core GEMM on s2 (independent of edge chain)
    cudaEventRecord(evFork, 0);
    cudaStreamWaitEvent(s2, evFork, 0);
    k_gemm<<<GEMM_TILES, 256, GEMM_SMEM, s2>>>(x, W);
    cudaEventRecord(evGemm, s2);

    // Edge chain on the captured main stream
    k_init<<<(NN + 255) / 256, 256>>>();
    k_count<<<(E4 + 255) / 256, 256>>>(dst, E4);
    k_scan1<<<SCAN_B, 1024>>>();
    k_scan2<<<1, 128>>>();
    k_scan3<<<SCAN_B, 1024>>>();
    k_fill<<<(E4 + 255) / 256, 256>>>(src, dst, ew, E4);
    k_degsum<<<(NN * 32 + 255) / 256, 256>>>();

    // Join
    cudaStreamWaitEvent(0, evGemm, 0);
    k_agg<<<(NN * 32 + 255) / 256, 256>>>(out, b);
}

// round 10
// speedup vs baseline: 1.1574x; 1.1574x over previous
#include <cuda_runtime.h>
#include <cuda_fp16.h>
#include <cstdint>

#define NN  100000
#define DD  128
#define EE  3200000
#define SCAN_B 98              // ceil(100000/1024)
#define GT 1563                // ceil(100000/64) gemm tiles (M=64)
#define XSTR 132               // padded row stride (words)
#define GEMM_SMEM ((128 * XSTR + 64 * XSTR) * 4)   // 101376 B

// Scratch (static device arrays; no allocs allowed)
__device__ float  g_deg[NN];
__device__ float  g_dinv[NN];
__device__ __half g_h16[(size_t)NN * DD];     // 25.6 MB (gather payload)
__device__ int    g_count[NN];
__device__ int    g_off[NN + 1];
__device__ int    g_cur[NN];
__device__ int    g_bsum[SCAN_B];
__device__ int    g_bpref[SCAN_B];
__device__ int2   g_csr[EE];                  // (src, w*dinv[src]) 25.6 MB

__device__ __forceinline__ unsigned f2tf32(float f) {
    unsigned u;
    asm("cvt.rna.tf32.f32 %0, %1;" : "=r"(u) : "f"(f));
    return u;
}

// ---------------------------------------------------------------------------
__global__ void k_init() {
    int i = blockIdx.x * blockDim.x + threadIdx.x;
    if (i < NN) { g_deg[i] = 1.0f; g_count[i] = 0; }
}

// deg[dst] += w  (float atomics only; runs on s2)
__global__ void k_deg(const int* __restrict__ dst,
                      const float* __restrict__ w, int E4) {
    int i = blockIdx.x * blockDim.x + threadIdx.x;
    if (i >= E4) return;
    const int4   d4 = ((const int4*)dst)[i];
    const float4 w4 = ((const float4*)w)[i];
    #pragma unroll
    for (int j = 0; j < 4; j++) {
        unsigned d = (unsigned)(&d4.x)[j];
        if (d < NN) atomicAdd(&g_deg[d], (&w4.x)[j]);
    }
}

__global__ void k_dinv() {
    int i = blockIdx.x * blockDim.x + threadIdx.x;
    if (i < NN) {
        float d = g_deg[i];
        g_dinv[i] = (d > 0.0f) ? rsqrtf(d) : 0.0f;
    }
}

// count[dst]++  (int atomics only; runs on main)
__global__ void k_count(const int* __restrict__ dst, int E4) {
    int i = blockIdx.x * blockDim.x + threadIdx.x;
    if (i >= E4) return;
    const int4 d4 = ((const int4*)dst)[i];
    #pragma unroll
    for (int j = 0; j < 4; j++) {
        unsigned d = (unsigned)(&d4.x)[j];
        if (d < NN) atomicAdd(&g_count[d], 1);
    }
}

// ---------------------------------------------------------------------------
__global__ void k_scan1() {
    __shared__ int swarp[32];
    const int t = threadIdx.x;
    const int idx = blockIdx.x * 1024 + t;
    int v = (idx < NN) ? g_count[idx] : 0;
    #pragma unroll
    for (int o = 16; o > 0; o >>= 1) v += __shfl_down_sync(~0u, v, o);
    if ((t & 31) == 0) swarp[t >> 5] = v;
    __syncthreads();
    if (t < 32) {
        int ss = swarp[t];
        #pragma unroll
        for (int o = 16; o > 0; o >>= 1) ss += __shfl_down_sync(~0u, ss, o);
        if (t == 0) g_bsum[blockIdx.x] = ss;
    }
}

__global__ void k_scan2() {
    __shared__ int s[128];
    const int t = threadIdx.x;
    s[t] = (t < SCAN_B) ? g_bsum[t] : 0;
    __syncthreads();
    #pragma unroll
    for (int o = 1; o < 128; o <<= 1) {
        int v = (t >= o) ? s[t - o] : 0;
        __syncthreads();
        s[t] += v;
        __syncthreads();
    }
    if (t < SCAN_B) g_bpref[t] = (t == 0) ? 0 : s[t - 1];
    if (t == 127) g_off[NN] = s[127];
}

__global__ void k_scan3() {
    __shared__ int swarp[33];
    const int t = threadIdx.x;
    const int lane = t & 31;
    const int wid = t >> 5;
    const int idx = blockIdx.x * 1024 + t;
    const int val = (idx < NN) ? g_count[idx] : 0;

    int v = val;
    #pragma unroll
    for (int o = 1; o < 32; o <<= 1) {
        int n = __shfl_up_sync(~0u, v, o);
        if (lane >= o) v += n;
    }
    if (lane == 31) swarp[wid] = v;
    __syncthreads();
    if (t < 32) {
        int s = swarp[t];
        #pragma unroll
        for (int o = 1; o < 32; o <<= 1) {
            int n = __shfl_up_sync(~0u, s, o);
            if (t >= o) s += n;
        }
        swarp[t + 1] = s;
        if (t == 0) swarp[0] = 0;
    }
    __syncthreads();

    if (idx < NN) {
        int excl = g_bpref[blockIdx.x] + swarp[wid] + (v - val);
        g_off[idx] = excl;
        g_cur[idx] = excl;
    }
}

// ---------------------------------------------------------------------------
// CSR fill — g_csr[pos] = (src, w*dinv[src])   [dinv ready via event]
// ---------------------------------------------------------------------------
__global__ void k_fill(const int* __restrict__ src,
                       const int* __restrict__ dst,
                       const float* __restrict__ w, int E4) {
    int i = blockIdx.x * blockDim.x + threadIdx.x;
    if (i >= E4) return;
    const int4   s4 = ((const int4*)src)[i];
    const int4   d4 = ((const int4*)dst)[i];
    const float4 w4 = ((const float4*)w)[i];
    #pragma unroll
    for (int j = 0; j < 4; j++) {
        unsigned s = (unsigned)(&s4.x)[j];
        unsigned d = (unsigned)(&d4.x)[j];
        if (s >= NN || d >= NN) continue;
        int pos = atomicAdd(&g_cur[d], 1);
        float nm = (&w4.x)[j] * g_dinv[s];
        g_csr[pos] = make_int2((int)s, __float_as_int(nm));
    }
}

// ---------------------------------------------------------------------------
// GEMM (tf32 tensor cores, M-tile 64, 2 blocks/SM): h16 = fp16(x @ W)
// 8 warps: wm in {0,1} (32m each), wn in {0..3} (32n each). mma.m16n8k8.
// X pre-converted to tf32 at staging; inner loop is LDS+MMA only.
// ---------------------------------------------------------------------------
__global__ void __launch_bounds__(256, 2)
k_gemm(const float* __restrict__ x, const float* __restrict__ W) {
    extern __shared__ unsigned sm[];
    unsigned* Ws = sm;                 // [128][132] tf32
    unsigned* Xs = sm + 128 * XSTR;    // [64][132]  tf32

    const int t    = threadIdx.x;
    const int lane = t & 31;
    const int wid  = t >> 5;
    const int wm   = wid & 1;          // m offset wm*32
    const int wn   = wid >> 1;         // n offset wn*32
    const int grp  = lane >> 2;        // 0..7
    const int qd   = lane & 3;         // 0..3

    // Stage W once: Ws[k][n], 64 elems/thread
    #pragma unroll 4
    for (int i = 0; i < 64; i++) {
        int lin = i * 256 + t;
        int k = lin >> 7, n = lin & 127;
        Ws[k * XSTR + n] = f2tf32(W[lin]);
    }

    for (int tile = blockIdx.x; tile < GT; tile += gridDim.x) {
        const int row0 = tile * 64;

        __syncthreads();   // Xs reuse (also covers Ws staging on iter 0)
        // Stage X tile 64x128, converted to tf32 (8 float4 per thread)
        #pragma unroll
        for (int i = 0; i < 8; i++) {
            int lin  = i * 256 + t;       // 0..2047
            int row  = lin >> 5;
            int col4 = lin & 31;
            float4 v = make_float4(0.f, 0.f, 0.f, 0.f);
            if (row0 + row < NN)
                v = ((const float4*)(x + (size_t)(row0 + row) * DD))[col4];
            uint4 u;
            u.x = f2tf32(v.x); u.y = f2tf32(v.y);
            u.z = f2tf32(v.z); u.w = f2tf32(v.w);
            *(uint4*)(Xs + row * XSTR + col4 * 4) = u;
        }
        __syncthreads();

        float c[2][4][4];
        #pragma unroll
        for (int mt = 0; mt < 2; mt++)
            #pragma unroll
            for (int nt = 0; nt < 4; nt++)
                #pragma unroll
                for (int q = 0; q < 4; q++) c[mt][nt][q] = 0.0f;

        #pragma unroll
        for (int ks = 0; ks < 16; ks++) {
            unsigned a[2][4];
            #pragma unroll
            for (int mt = 0; mt < 2; mt++) {
                const int rb = wm * 32 + mt * 16 + grp;
                const int kb = ks * 8 + qd;
                a[mt][0] = Xs[rb * XSTR + kb];
                a[mt][1] = Xs[(rb + 8) * XSTR + kb];
                a[mt][2] = Xs[rb * XSTR + kb + 4];
                a[mt][3] = Xs[(rb + 8) * XSTR + kb + 4];
            }
            #pragma unroll
            for (int nt = 0; nt < 4; nt++) {
                const int nb = wn * 32 + nt * 8 + grp;
                const unsigned b0 = Ws[(ks * 8 + qd) * XSTR + nb];
                const unsigned b1 = Ws[(ks * 8 + qd + 4) * XSTR + nb];
                #pragma unroll
                for (int mt = 0; mt < 2; mt++) {
                    asm volatile(
                        "mma.sync.aligned.m16n8k8.row.col.f32.tf32.tf32.f32 "
                        "{%0,%1,%2,%3}, {%4,%5,%6,%7}, {%8,%9}, {%0,%1,%2,%3};"
                        : "+f"(c[mt][nt][0]), "+f"(c[mt][nt][1]),
                          "+f"(c[mt][nt][2]), "+f"(c[mt][nt][3])
                        : "r"(a[mt][0]), "r"(a[mt][1]), "r"(a[mt][2]), "r"(a[mt][3]),
                          "r"(b0), "r"(b1));
                }
            }
        }

        // Epilogue: fp16 stores, cols (2*qd, 2*qd+1) contiguous per reg pair
        #pragma unroll
        for (int mt = 0; mt < 2; mt++) {
            const int r0g = row0 + wm * 32 + mt * 16 + grp;
            #pragma unroll
            for (int nt = 0; nt < 4; nt++) {
                const int col = wn * 32 + nt * 8 + 2 * qd;
                if (r0g < NN) {
                    __half2 h = __float22half2_rn(make_float2(c[mt][nt][0], c[mt][nt][1]));
                    *(__half2*)(g_h16 + (size_t)r0g * DD + col) = h;
                }
                if (r0g + 8 < NN) {
                    __half2 h = __float22half2_rn(make_float2(c[mt][nt][2], c[mt][nt][3]));
                    *(__half2*)(g_h16 + (size_t)(r0g + 8) * DD + col) = h;
                }
            }
        }
    }
}

// ---------------------------------------------------------------------------
// agg — one warp per node:
// out = b + dinv*(dinv*h16[node] + sum_e nm_e*h16[src_e]).  Pure store.
// ---------------------------------------------------------------------------
__global__ void k_agg(float* __restrict__ out, const float* __restrict__ b) {
    const int node = (blockIdx.x * blockDim.x + threadIdx.x) >> 5;
    const int lane = threadIdx.x & 31;
    if (node >= NN) return;

    const int beg = g_off[node];
    const int end = g_off[node + 1];
    const float dd = g_dinv[node];

    float4 acc;
    {
        const uint2 hv = ((const uint2*)(g_h16 + (size_t)node * DD))[lane];
        const float2 v0 = __half22float2(*(const __half2*)&hv.x);
        const float2 v1 = __half22float2(*(const __half2*)&hv.y);
        acc.x = dd * v0.x; acc.y = dd * v0.y;
        acc.z = dd * v1.x; acc.w = dd * v1.y;
    }

    #pragma unroll 4
    for (int e = beg; e < end; e++) {
        const int2  p  = g_csr[e];
        const float nm = __int_as_float(p.y);
        const uint2 hv = ((const uint2*)(g_h16 + (size_t)p.x * DD))[lane];
        const float2 v0 = __half22float2(*(const __half2*)&hv.x);
        const float2 v1 = __half22float2(*(const __half2*)&hv.y);
        acc.x += nm * v0.x;
        acc.y += nm * v0.y;
        acc.z += nm * v1.x;
        acc.w += nm * v1.y;
    }

    const float4 b4 = ((const float4*)b)[lane];
    float4 o;
    o.x = b4.x + dd * acc.x;
    o.y = b4.y + dd * acc.y;
    o.z = b4.z + dd * acc.z;
    o.w = b4.w + dd * acc.w;
    ((float4*)(out + (size_t)node * DD))[lane] = o;
}

// ---------------------------------------------------------------------------
extern "C" void kernel_launch(void* const* d_in, const int* in_sizes, int n_in,
                              void* d_out, int out_size) {
    const float* x  = nullptr;
    const int*   ei = nullptr;
    const float* ew = nullptr;
    const float* W  = nullptr;
    const float* b  = nullptr;
    int E = 0;
    for (int i = 0; i < n_in; i++) {
        const int sz = in_sizes[i];
        if      (sz == NN * DD)   x  = (const float*)d_in[i];
        else if (sz == 2 * EE)    ei = (const int*)d_in[i];
        else if (sz == EE)        { ew = (const float*)d_in[i]; E = sz; }
        else if (sz == DD * DD)   W  = (const float*)d_in[i];
        else if (sz == DD)        b  = (const float*)d_in[i];
    }
    if (!x || !ei || !ew || !W || !b) return;

    float* out = (float*)d_out;
    const int* src = ei;
    const int* dst = ei + E;
    const int E4 = E / 4;

    static cudaStream_t s2 = nullptr, s3 = nullptr;
    static cudaEvent_t evFork = nullptr, evInit = nullptr,
                       evDinv = nullptr, evGemm = nullptr;
    static bool setup = false;
    if (!setup) {
        cudaFuncSetAttribute(k_gemm, cudaFuncAttributeMaxDynamicSharedMemorySize,
                             GEMM_SMEM);
        cudaStreamCreateWithFlags(&s2, cudaStreamNonBlocking);
        cudaStreamCreateWithFlags(&s3, cudaStreamNonBlocking);
        cudaEventCreateWithFlags(&evFork, cudaEventDisableTiming);
        cudaEventCreateWithFlags(&evInit, cudaEventDisableTiming);
        cudaEventCreateWithFlags(&evDinv, cudaEventDisableTiming);
        cudaEventCreateWithFlags(&evGemm, cudaEventDisableTiming);
        setup = true;
    }

    // Fork point: all side streams must branch off the capture stream.
    cudaEventRecord(evFork, 0);

    // s3: GEMM (independent of edge chain)
    cudaStreamWaitEvent(s3, evFork, 0);
    k_gemm<<<296, 256, GEMM_SMEM, s3>>>(x, W);
    cudaEventRecord(evGemm, s3);

    // main: init, then fork deg-chain to s2
    k_init<<<(NN + 255) / 256, 256>>>();
    cudaEventRecord(evInit, 0);
    cudaStreamWaitEvent(s2, evInit, 0);
    k_deg<<<(E4 + 255) / 256, 256, 0, s2>>>(dst, ew, E4);
    k_dinv<<<(NN + 255) / 256, 256, 0, s2>>>();
    cudaEventRecord(evDinv, s2);

    // main: count + scan
    k_count<<<(E4 + 255) / 256, 256>>>(dst, E4);
    k_scan1<<<SCAN_B, 1024>>>();
    k_scan2<<<1, 128>>>();
    k_scan3<<<SCAN_B, 1024>>>();

    // fill needs dinv (s2)
    cudaStreamWaitEvent(0, evDinv, 0);
    k_fill<<<(E4 + 255) / 256, 256>>>(src, dst, ew, E4);

    // agg needs gemm (s3) + fill (main)
    cudaStreamWaitEvent(0, evGemm, 0);
    k_agg<<<(NN * 32 + 255) / 256, 256>>>(out, b);
}